// round 12
// baseline (speedup 1.0000x reference)
#include <cuda_runtime.h>
#include <cuda_fp16.h>

#define NMAX 100000
#define EMAX 1600000
#define CMAX 128

// Scratch (__device__ globals: allocation-free rule)
__device__ __half d_G[(size_t)NMAX * CMAX];       // messages (half)
__device__ __half d_B1[(size_t)NMAX * CMAX];      // activations (half)
__device__ __half d_B2[(size_t)NMAX * CMAX];
__device__ float  d_dinv[NMAX];
__device__ int    d_cnt[NMAX];
__device__ int    d_pos[EMAX];                    // edge slot within its dst bucket
__device__ int    d_off[NMAX + 1];
__device__ int    d_csr[EMAX];
__device__ int    d_blk[128];
__device__ int    d_blk2[128];
__device__ unsigned d_gmin[64];
__device__ int    d_done;

__device__ __forceinline__ unsigned enc_f(float f) {
    unsigned u = __float_as_uint(f);
    return (u & 0x80000000u) ? ~u : (u | 0x80000000u);
}
__device__ __forceinline__ float dec_f(unsigned e) {
    unsigned u = (e & 0x80000000u) ? (e ^ 0x80000000u) : ~e;
    return __uint_as_float(u);
}

// 4 halves (8B) from fp32 or half source row
__device__ __forceinline__ uint2 loadH4(const float* A, size_t row, int k4) {
    float4 v = __ldg((const float4*)(A + row * 128) + k4);
    __half2 h0 = __floats2half2_rn(v.x, v.y);
    __half2 h1 = __floats2half2_rn(v.z, v.w);
    uint2 r;
    r.x = *(unsigned*)&h0;
    r.y = *(unsigned*)&h1;
    return r;
}
__device__ __forceinline__ uint2 loadH4(const __half* A, size_t row, int k4) {
    return __ldg((const uint2*)(A + row * 128) + k4);
}

// ================= CSR scans =================
__global__ void k_scan1(int N) {
    __shared__ int sh[256];
    int t = threadIdx.x;
    int base = blockIdx.x * 1024 + t * 4;
    int c0 = 0, c1 = 0, c2 = 0, c3 = 0;
    if (base + 3 < N) {
        int4 v = *(const int4*)&d_cnt[base];
        c0 = v.x; c1 = v.y; c2 = v.z; c3 = v.w;
    } else {
        if (base + 0 < N) c0 = d_cnt[base + 0];
        if (base + 1 < N) c1 = d_cnt[base + 1];
        if (base + 2 < N) c2 = d_cnt[base + 2];
        if (base + 3 < N) c3 = d_cnt[base + 3];
    }
    int s = c0 + c1 + c2 + c3;
    sh[t] = s;
    __syncthreads();
    for (int d = 1; d < 256; d <<= 1) {
        int v = (t >= d) ? sh[t - d] : 0;
        __syncthreads();
        sh[t] += v;
        __syncthreads();
    }
    int excl = sh[t] - s;
    if (base + 0 < N) d_off[base + 0] = excl;
    if (base + 1 < N) d_off[base + 1] = excl + c0;
    if (base + 2 < N) d_off[base + 2] = excl + c0 + c1;
    if (base + 3 < N) d_off[base + 3] = excl + c0 + c1 + c2;
    if (t == 255) d_blk[blockIdx.x] = sh[255];
}

__global__ void k_scan2(int nblk) {
    __shared__ int sh[128];
    int t = threadIdx.x;
    int v = (t < nblk) ? d_blk[t] : 0;
    sh[t] = v;
    __syncthreads();
    for (int d = 1; d < 128; d <<= 1) {
        int u = (t >= d) ? sh[t - d] : 0;
        __syncthreads();
        sh[t] += u;
        __syncthreads();
    }
    d_blk2[t] = sh[t] - v;
}

// Also: computes dinv, zeroes d_cnt for graph replay, inits gmin + done counter.
__global__ void k_scan3(int N, int E) {
    int i = blockIdx.x * blockDim.x + threadIdx.x;
    if (i < N) {
        d_off[i] += d_blk2[i >> 10];
        d_dinv[i] = rsqrtf((float)d_cnt[i] + 1.0f);  // +1 self-loop
        d_cnt[i] = 0;                                 // self-clean for replay
    }
    if (i == 0) {
        d_off[N] = E;
        d_done = 0;
    }
    if (blockIdx.x == 0 && threadIdx.x < 64) d_gmin[threadIdx.x] = 0xFFFFFFFFu;
}

// CSR fill, atomic-free: slot was recorded during the fused histogram.
__global__ void k_fill2(const int* __restrict__ src, const int* __restrict__ dst, int E) {
    int i = blockIdx.x * blockDim.x + threadIdx.x;
    if (i >= E) return;
    d_csr[d_off[dst[i]] + d_pos[i]] = src[i];
}

// ================= tensor-core GEMM =================
// g[row] = half((DINV ? dinv[row] : 1) * (A[row] @ W))
// 256 threads; tile = 128 rows x COLS; mma.sync.m16n8k16 (f16 in, f32 accum).
// HIST: blocks with bid < xBlocks do the degree histogram (and record d_pos).
template <int COLS, bool HIST, bool DINV, typename AT>
__global__ void __launch_bounds__(256)
k_gemm_mma(const AT* __restrict__ A, const float* __restrict__ W,
           __half* __restrict__ g, int N,
           const int* __restrict__ dstp, int E, int xBlocks)
{
    if (HIST && (int)blockIdx.x < xBlocks) {
        for (int i = blockIdx.x * 256 + threadIdx.x; i < E; i += xBlocks * 256) {
            int d = dstp[i];
            d_pos[i] = atomicAdd(&d_cnt[d], 1);
        }
        return;
    }
    constexpr int AROW = 272;
    constexpr int WROW = (COLS == 128) ? 272 : 144;
    constexpr int NT = COLS / 8;

    extern __shared__ char sm[];
    char* smA = sm;
    char* smW = sm + 128 * AROW;
    const unsigned sA = (unsigned)__cvta_generic_to_shared(smA);
    const unsigned sW = (unsigned)__cvta_generic_to_shared(smW);

    const int tid = threadIdx.x;
    const int base = (blockIdx.x - (HIST ? xBlocks : 0)) * 128;

    for (int i = tid; i < 128 * 32; i += 256) {
        int r = i >> 5, k4 = i & 31;
        int row = base + r;
        uint2 v = make_uint2(0u, 0u);
        if (row < N) v = loadH4(A, (size_t)row, k4);
        *(uint2*)(smA + r * AROW + k4 * 8) = v;
    }
    for (int i = tid; i < 128 * COLS / 4; i += 256) {
        int r = i / (COLS / 4), n4 = i % (COLS / 4);
        float4 v = __ldg((const float4*)W + i);
        __half2 h0 = __floats2half2_rn(v.x, v.y);
        __half2 h1 = __floats2half2_rn(v.z, v.w);
        uint2 u;
        u.x = *(unsigned*)&h0;
        u.y = *(unsigned*)&h1;
        *(uint2*)(smW + r * WROW + n4 * 8) = u;
    }
    __syncthreads();

    const int warp = tid >> 5;
    const int lane = tid & 31;
    const int warprow = warp * 16;
    const int lr = lane & 7;
    const int sel = lane >> 3;
    const int selLo = sel & 1;
    const int selHi = sel >> 1;

    float c[NT][4];
#pragma unroll
    for (int n = 0; n < NT; n++)
#pragma unroll
        for (int q = 0; q < 4; q++) c[n][q] = 0.f;

#pragma unroll
    for (int ks = 0; ks < 8; ks++) {
        unsigned a0, a1, a2, a3;
        unsigned aaddr = sA + (warprow + lr + selLo * 8) * AROW + ks * 32 + selHi * 16;
        asm volatile("ldmatrix.sync.aligned.m8n8.x4.shared.b16 {%0,%1,%2,%3}, [%4];"
                     : "=r"(a0), "=r"(a1), "=r"(a2), "=r"(a3) : "r"(aaddr));
#pragma unroll
        for (int p = 0; p < NT / 2; p++) {
            unsigned b0, b1, b2, b3;
            unsigned baddr = sW + (ks * 16 + lr + selLo * 8) * WROW + p * 32 + selHi * 16;
            asm volatile("ldmatrix.sync.aligned.m8n8.x4.trans.shared.b16 {%0,%1,%2,%3}, [%4];"
                         : "=r"(b0), "=r"(b1), "=r"(b2), "=r"(b3) : "r"(baddr));
            asm volatile("mma.sync.aligned.m16n8k16.row.col.f32.f16.f16.f32 "
                         "{%0,%1,%2,%3}, {%4,%5,%6,%7}, {%8,%9}, {%0,%1,%2,%3};"
                         : "+f"(c[2 * p][0]), "+f"(c[2 * p][1]), "+f"(c[2 * p][2]), "+f"(c[2 * p][3])
                         : "r"(a0), "r"(a1), "r"(a2), "r"(a3), "r"(b0), "r"(b1));
            asm volatile("mma.sync.aligned.m16n8k16.row.col.f32.f16.f16.f32 "
                         "{%0,%1,%2,%3}, {%4,%5,%6,%7}, {%8,%9}, {%0,%1,%2,%3};"
                         : "+f"(c[2 * p + 1][0]), "+f"(c[2 * p + 1][1]), "+f"(c[2 * p + 1][2]), "+f"(c[2 * p + 1][3])
                         : "r"(a0), "r"(a1), "r"(a2), "r"(a3), "r"(b2), "r"(b3));
        }
    }

    const int gq = lane >> 2;
    const int tig = lane & 3;
    int row0 = base + warprow + gq;
    int row1 = row0 + 8;
    float dv0 = 1.f, dv1 = 1.f;
    if (DINV) {
        dv0 = (row0 < N) ? d_dinv[row0] : 0.f;
        dv1 = (row1 < N) ? d_dinv[row1] : 0.f;
    }
#pragma unroll
    for (int n = 0; n < NT; n++) {
        int col = n * 8 + 2 * tig;
        if (row0 < N) {
            __half2 h = __floats2half2_rn(c[n][0] * dv0, c[n][1] * dv0);
            *(__half2*)(g + (size_t)row0 * COLS + col) = h;
        }
        if (row1 < N) {
            __half2 h = __floats2half2_rn(c[n][2] * dv1, c[n][3] * dv1);
            *(__half2*)(g + (size_t)row1 * COLS + col) = h;
        }
    }
}

// ================= CSR aggregate (LDG.128 cooperative gather) ====================
__device__ __forceinline__ void acc_u4(float* a, uint4 v) {
    float2 f;
    f = __half22float2(*(__half2*)&v.x); a[0] += f.x; a[1] += f.y;
    f = __half22float2(*(__half2*)&v.y); a[2] += f.x; a[3] += f.y;
    f = __half22float2(*(__half2*)&v.z); a[4] += f.x; a[5] += f.y;
    f = __half22float2(*(__half2*)&v.w); a[6] += f.x; a[7] += f.y;
}
__device__ __forceinline__ void acc_u4s(float* a, uint4 v, float s) {
    float2 f;
    f = __half22float2(*(__half2*)&v.x); a[0] = fmaf(f.x, s, a[0]); a[1] = fmaf(f.y, s, a[1]);
    f = __half22float2(*(__half2*)&v.y); a[2] = fmaf(f.x, s, a[2]); a[3] = fmaf(f.y, s, a[3]);
    f = __half22float2(*(__half2*)&v.z); a[4] = fmaf(f.x, s, a[4]); a[5] = fmaf(f.y, s, a[5]);
    f = __half22float2(*(__half2*)&v.w); a[6] = fmaf(f.x, s, a[6]); a[7] = fmaf(f.y, s, a[7]);
}

// 128 cols: half-warp (16 lanes x uint4 = 256B) per row, 2 neighbors per LDG.128.
// SRCSCALE: messages are unscaled (layer 1); multiply each neighbor by dinv[nb].
template <bool SRCSCALE>
__global__ void k_agg128(const __half* __restrict__ g, const float* __restrict__ bias,
                         __half* __restrict__ out, int N)
{
    int node = (blockIdx.x * blockDim.x + threadIdx.x) >> 5;
    int lane = threadIdx.x & 31;
    if (node >= N) return;
    const uint4* gp = (const uint4*)g;
    const int hf = lane >> 4;
    const int sl = lane & 15;
    const float dvn = d_dinv[node];

    float a[8] = {0, 0, 0, 0, 0, 0, 0, 0};
    if (hf == 0) {                                       // self-loop once
        uint4 v = __ldg(&gp[(size_t)node * 16 + sl]);
        if (SRCSCALE) acc_u4s(a, v, dvn); else acc_u4(a, v);
    }

    int s = d_off[node], e = d_off[node + 1];
    int j = s;
    int c0, c1, c2, c3, c4, c5, c6, c7;
    bool have = (j + 8 <= e);
    if (have) {
        c0 = __ldg(d_csr + j);     c1 = __ldg(d_csr + j + 1);
        c2 = __ldg(d_csr + j + 2); c3 = __ldg(d_csr + j + 3);
        c4 = __ldg(d_csr + j + 4); c5 = __ldg(d_csr + j + 5);
        c6 = __ldg(d_csr + j + 6); c7 = __ldg(d_csr + j + 7);
    }
    while (have) {
        bool nxt = (j + 16 <= e);
        int m0, m1, m2, m3, m4, m5, m6, m7;
        if (nxt) {
            m0 = __ldg(d_csr + j + 8);  m1 = __ldg(d_csr + j + 9);
            m2 = __ldg(d_csr + j + 10); m3 = __ldg(d_csr + j + 11);
            m4 = __ldg(d_csr + j + 12); m5 = __ldg(d_csr + j + 13);
            m6 = __ldg(d_csr + j + 14); m7 = __ldg(d_csr + j + 15);
        }
        int e0 = hf ? c1 : c0;
        int e1 = hf ? c3 : c2;
        int e2 = hf ? c5 : c4;
        int e3 = hf ? c7 : c6;
        uint4 v0 = __ldg(&gp[(size_t)e0 * 16 + sl]);
        uint4 v1 = __ldg(&gp[(size_t)e1 * 16 + sl]);
        uint4 v2 = __ldg(&gp[(size_t)e2 * 16 + sl]);
        uint4 v3 = __ldg(&gp[(size_t)e3 * 16 + sl]);
        if (SRCSCALE) {
            acc_u4s(a, v0, __ldg(d_dinv + e0));
            acc_u4s(a, v1, __ldg(d_dinv + e1));
            acc_u4s(a, v2, __ldg(d_dinv + e2));
            acc_u4s(a, v3, __ldg(d_dinv + e3));
        } else {
            acc_u4(a, v0); acc_u4(a, v1); acc_u4(a, v2); acc_u4(a, v3);
        }
        c0 = m0; c1 = m1; c2 = m2; c3 = m3;
        c4 = m4; c5 = m5; c6 = m6; c7 = m7;
        j += 8;
        have = nxt;
    }
    for (; j + 2 <= e; j += 2) {
        int n0 = __ldg(d_csr + j), n1 = __ldg(d_csr + j + 1);
        int nb = hf ? n1 : n0;
        uint4 v = __ldg(&gp[(size_t)nb * 16 + sl]);
        if (SRCSCALE) acc_u4s(a, v, __ldg(d_dinv + nb)); else acc_u4(a, v);
    }
    if (j < e && hf == 0) {
        int nb = __ldg(d_csr + j);
        uint4 v = __ldg(&gp[(size_t)nb * 16 + sl]);
        if (SRCSCALE) acc_u4s(a, v, __ldg(d_dinv + nb)); else acc_u4(a, v);
    }
#pragma unroll
    for (int i = 0; i < 8; i++)
        a[i] += __shfl_xor_sync(0xFFFFFFFFu, a[i], 16);

    if (hf == 0) {
        float4 b0 = __ldg((const float4*)bias + sl * 2);
        float4 b1 = __ldg((const float4*)bias + sl * 2 + 1);
        __half2 h[4];
        h[0] = __floats2half2_rn(fmaxf(fmaf(a[0], dvn, b0.x), 0.f),
                                 fmaxf(fmaf(a[1], dvn, b0.y), 0.f));
        h[1] = __floats2half2_rn(fmaxf(fmaf(a[2], dvn, b0.z), 0.f),
                                 fmaxf(fmaf(a[3], dvn, b0.w), 0.f));
        h[2] = __floats2half2_rn(fmaxf(fmaf(a[4], dvn, b1.x), 0.f),
                                 fmaxf(fmaf(a[5], dvn, b1.y), 0.f));
        h[3] = __floats2half2_rn(fmaxf(fmaf(a[6], dvn, b1.z), 0.f),
                                 fmaxf(fmaf(a[7], dvn, b1.w), 0.f));
        ((uint4*)out)[(size_t)node * 16 + sl] = *(uint4*)h;
    }
}

// 64 cols: quarter-warp gather + fused min-pool + fused final output (last block).
__global__ void k_agg64min(const __half* __restrict__ g, const float* __restrict__ b3,
                           float* __restrict__ out, int N)
{
    __shared__ unsigned sMin[64];
    __shared__ bool lastBlk;
    int tid = threadIdx.x;
    if (tid < 64) sMin[tid] = 0xFFFFFFFFu;
    __syncthreads();

    int node = (blockIdx.x * blockDim.x + tid) >> 5;
    int lane = tid & 31;
    if (node < N) {
        const uint4* gp = (const uint4*)g;
        const int q = lane >> 3;
        const int sl = lane & 7;

        float a[8] = {0, 0, 0, 0, 0, 0, 0, 0};
        if (q == 0)
            acc_u4(a, __ldg(&gp[(size_t)node * 8 + sl]));

        int s = d_off[node], e = d_off[node + 1];
        int j = s;
        int c0, c1, c2, c3, c4, c5, c6, c7;
        bool have = (j + 8 <= e);
        if (have) {
            c0 = __ldg(d_csr + j);     c1 = __ldg(d_csr + j + 1);
            c2 = __ldg(d_csr + j + 2); c3 = __ldg(d_csr + j + 3);
            c4 = __ldg(d_csr + j + 4); c5 = __ldg(d_csr + j + 5);
            c6 = __ldg(d_csr + j + 6); c7 = __ldg(d_csr + j + 7);
        }
        while (have) {
            bool nxt = (j + 16 <= e);
            int m0, m1, m2, m3, m4, m5, m6, m7;
            if (nxt) {
                m0 = __ldg(d_csr + j + 8);  m1 = __ldg(d_csr + j + 9);
                m2 = __ldg(d_csr + j + 10); m3 = __ldg(d_csr + j + 11);
                m4 = __ldg(d_csr + j + 12); m5 = __ldg(d_csr + j + 13);
                m6 = __ldg(d_csr + j + 14); m7 = __ldg(d_csr + j + 15);
            }
            int ea = (q == 0) ? c0 : (q == 1) ? c1 : (q == 2) ? c2 : c3;
            int eb = (q == 0) ? c4 : (q == 1) ? c5 : (q == 2) ? c6 : c7;
            uint4 va = __ldg(&gp[(size_t)ea * 8 + sl]);
            uint4 vb = __ldg(&gp[(size_t)eb * 8 + sl]);
            acc_u4(a, va); acc_u4(a, vb);
            c0 = m0; c1 = m1; c2 = m2; c3 = m3;
            c4 = m4; c5 = m5; c6 = m6; c7 = m7;
            j += 8;
            have = nxt;
        }
        for (; j + 4 <= e; j += 4) {
            int n0 = __ldg(d_csr + j),     n1 = __ldg(d_csr + j + 1);
            int n2 = __ldg(d_csr + j + 2), n3 = __ldg(d_csr + j + 3);
            int nb = (q == 0) ? n0 : (q == 1) ? n1 : (q == 2) ? n2 : n3;
            acc_u4(a, __ldg(&gp[(size_t)nb * 8 + sl]));
        }
        int rem = e - j;
        if (q < rem) {
            int nb = __ldg(d_csr + j + q);
            acc_u4(a, __ldg(&gp[(size_t)nb * 8 + sl]));
        }
#pragma unroll
        for (int i = 0; i < 8; i++) {
            a[i] += __shfl_xor_sync(0xFFFFFFFFu, a[i], 8);
            a[i] += __shfl_xor_sync(0xFFFFFFFFu, a[i], 16);
        }
        if (q == 0) {
            float dv = d_dinv[node];
#pragma unroll
            for (int i = 0; i < 8; i++)
                atomicMin(&sMin[sl * 8 + i], enc_f(a[i] * dv));
        }
    }
    __syncthreads();
    if (tid < 64) atomicMin(&d_gmin[tid], sMin[tid]);
    __threadfence();
    __syncthreads();
    if (tid == 0) {
        int old = atomicAdd(&d_done, 1);
        lastBlk = (old == (int)gridDim.x - 1);
    }
    __syncthreads();
    if (lastBlk) {
        __threadfence();
        if (tid < 64) out[tid] = dec_f(d_gmin[tid]) + __ldg(b3 + tid);
    }
}

extern "C" void kernel_launch(void* const* d_in, const int* in_sizes, int n_in,
                              void* d_out, int out_size)
{
    const float* x  = (const float*)d_in[0];
    const int*   ei = (const int*)d_in[1];
    const float* W1 = (const float*)d_in[2];
    const float* b1 = (const float*)d_in[3];
    const float* W2 = (const float*)d_in[4];
    const float* b2 = (const float*)d_in[5];
    const float* W3 = (const float*)d_in[6];
    const float* b3 = (const float*)d_in[7];
    float* out = (float*)d_out;

    int N = in_sizes[0] / 128;
    int E = in_sizes[1] / 2;
    const int* src = ei;
    const int* dst = ei + E;

    __half *B1, *B2, *G;
    cudaGetSymbolAddress((void**)&B1, d_B1);
    cudaGetSymbolAddress((void**)&B2, d_B2);
    cudaGetSymbolAddress((void**)&G, d_G);

    const int smem128 = 128 * 272 + 128 * 272;
    const int smem64  = 128 * 272 + 128 * 144;
    cudaFuncSetAttribute(k_gemm_mma<128, true,  false, float>,  cudaFuncAttributeMaxDynamicSharedMemorySize, smem128);
    cudaFuncSetAttribute(k_gemm_mma<128, false, true,  __half>, cudaFuncAttributeMaxDynamicSharedMemorySize, smem128);
    cudaFuncSetAttribute(k_gemm_mma<64,  false, true,  __half>, cudaFuncAttributeMaxDynamicSharedMemorySize, smem64);

    int gb = (N + 127) / 128;
    const int histBlocks = 768;

    // Layer-1 GEMM (unscaled epilogue) with degree histogram fused at low bids.
    k_gemm_mma<128, true, false, float><<<gb + histBlocks, 256, smem128>>>(x, W1, G, N, dst, E, histBlocks);

    // CSR scans (dinv ready after scan3), then atomic-free fill.
    int nblk = (N + 1023) / 1024;
    k_scan1<<<nblk, 256>>>(N);
    k_scan2<<<1, 128>>>(nblk);
    k_scan3<<<(N + 255) / 256, 256>>>(N, E);
    k_fill2<<<(E + 255) / 256, 256>>>(src, dst, E);

    // Layer 1 aggregate (applies dinv[src] per neighbor + dinv[dst] post)
    k_agg128<true><<<(N * 32 + 255) / 256, 256>>>(G, b1, B2, N);

    // Layer 2
    k_gemm_mma<128, false, true, __half><<<gb, 256, smem128>>>(B2, W2, G, N, nullptr, 0, 0);
    k_agg128<false><<<(N * 32 + 255) / 256, 256>>>(G, b2, B1, N);

    // Layer 3 (64 cols) + fused min-pool + fused final
    k_gemm_mma<64, false, true, __half><<<gb, 256, smem64>>>(B1, W3, G, N, nullptr, 0, 0);
    k_agg64min<<<(N * 32 + 255) / 256, 256>>>(G, b3, out, N);
}

// round 13
// speedup vs baseline: 1.4274x; 1.4274x over previous
#include <cuda_runtime.h>
#include <cuda_fp16.h>

#define NMAX 100000
#define EMAX 1600000
#define CMAX 128

// Scratch (__device__ globals: allocation-free rule)
__device__ __half d_G[(size_t)NMAX * CMAX];       // messages (half)
__device__ __half d_B1[(size_t)NMAX * CMAX];      // activations (half)
__device__ __half d_B2[(size_t)NMAX * CMAX];
__device__ float  d_dinv[NMAX];
__device__ int    d_cnt[NMAX];
__device__ int    d_cur[NMAX];
__device__ int    d_off[NMAX + 1];
__device__ int    d_csr[EMAX];
__device__ int    d_blk[128];
__device__ int    d_blk2[128];
__device__ unsigned d_gmin[64];
__device__ int    d_done;

__device__ __forceinline__ unsigned enc_f(float f) {
    unsigned u = __float_as_uint(f);
    return (u & 0x80000000u) ? ~u : (u | 0x80000000u);
}
__device__ __forceinline__ float dec_f(unsigned e) {
    unsigned u = (e & 0x80000000u) ? (e ^ 0x80000000u) : ~e;
    return __uint_as_float(u);
}

// 4 halves (8B) from fp32 or half source row
__device__ __forceinline__ uint2 loadH4(const float* A, size_t row, int k4) {
    float4 v = __ldg((const float4*)(A + row * 128) + k4);
    __half2 h0 = __floats2half2_rn(v.x, v.y);
    __half2 h1 = __floats2half2_rn(v.z, v.w);
    uint2 r;
    r.x = *(unsigned*)&h0;
    r.y = *(unsigned*)&h1;
    return r;
}
__device__ __forceinline__ uint2 loadH4(const __half* A, size_t row, int k4) {
    return __ldg((const uint2*)(A + row * 128) + k4);
}

// ================= degree histogram (vectorized, fire-and-forget REDG) ==========
__global__ void k_hist(const int* __restrict__ dst, int E) {
    int i = blockIdx.x * blockDim.x + threadIdx.x;
    int E4 = E >> 2;
    if (i < E4) {
        int4 v = __ldg((const int4*)dst + i);
        atomicAdd(&d_cnt[v.x], 1);
        atomicAdd(&d_cnt[v.y], 1);
        atomicAdd(&d_cnt[v.z], 1);
        atomicAdd(&d_cnt[v.w], 1);
    }
    int t = E4 * 4 + i;                     // tail (E % 4 elements)
    if (i < (E & 3)) atomicAdd(&d_cnt[dst[t]], 1);
}

// ================= CSR scans =================
__global__ void k_scan1(int N) {
    __shared__ int sh[256];
    int t = threadIdx.x;
    int base = blockIdx.x * 1024 + t * 4;
    int c0 = 0, c1 = 0, c2 = 0, c3 = 0;
    if (base + 3 < N) {
        int4 v = *(const int4*)&d_cnt[base];
        c0 = v.x; c1 = v.y; c2 = v.z; c3 = v.w;
    } else {
        if (base + 0 < N) c0 = d_cnt[base + 0];
        if (base + 1 < N) c1 = d_cnt[base + 1];
        if (base + 2 < N) c2 = d_cnt[base + 2];
        if (base + 3 < N) c3 = d_cnt[base + 3];
    }
    int s = c0 + c1 + c2 + c3;
    sh[t] = s;
    __syncthreads();
    for (int d = 1; d < 256; d <<= 1) {
        int v = (t >= d) ? sh[t - d] : 0;
        __syncthreads();
        sh[t] += v;
        __syncthreads();
    }
    int excl = sh[t] - s;
    if (base + 0 < N) d_off[base + 0] = excl;
    if (base + 1 < N) d_off[base + 1] = excl + c0;
    if (base + 2 < N) d_off[base + 2] = excl + c0 + c1;
    if (base + 3 < N) d_off[base + 3] = excl + c0 + c1 + c2;
    if (t == 255) d_blk[blockIdx.x] = sh[255];
}

__global__ void k_scan2(int nblk) {
    __shared__ int sh[128];
    int t = threadIdx.x;
    int v = (t < nblk) ? d_blk[t] : 0;
    sh[t] = v;
    __syncthreads();
    for (int d = 1; d < 128; d <<= 1) {
        int u = (t >= d) ? sh[t - d] : 0;
        __syncthreads();
        sh[t] += u;
        __syncthreads();
    }
    d_blk2[t] = sh[t] - v;
}

// Also: computes dinv, zeroes d_cnt/d_cur for graph replay, inits gmin + done.
__global__ void k_scan3(int N, int E) {
    int i = blockIdx.x * blockDim.x + threadIdx.x;
    if (i < N) {
        d_off[i] += d_blk2[i >> 10];
        d_dinv[i] = rsqrtf((float)d_cnt[i] + 1.0f);  // +1 self-loop
        d_cnt[i] = 0;                                 // self-clean for replay
        d_cur[i] = 0;
    }
    if (i == 0) {
        d_off[N] = E;
        d_done = 0;
    }
    if (blockIdx.x == 0 && threadIdx.x < 64) d_gmin[threadIdx.x] = 0xFFFFFFFFu;
}

// ================= tensor-core GEMM =================
// g[row] = half(dinv[row] * (A[row] @ W)); A: [N][128] (fp32 or half), W: [128][COLS] fp32.
// 256 threads; tile = 128 rows x COLS; mma.sync.m16n8k16 (f16 in, f32 accum).
// FILL: blocks with bid < fillBlocks do the CSR fill instead (low bids start
// in the first wave, overlapping the GEMM; scan3 already ran).
template <int COLS, bool FILL, typename AT>
__global__ void __launch_bounds__(256)
k_gemm_mma(const AT* __restrict__ A, const float* __restrict__ W,
           __half* __restrict__ g, int N,
           const int* __restrict__ src, const int* __restrict__ dstp, int E, int fillBlocks)
{
    if (FILL && (int)blockIdx.x < fillBlocks) {
        for (int i = blockIdx.x * 256 + threadIdx.x; i < E; i += fillBlocks * 256) {
            int d = dstp[i];
            int p = atomicAdd(&d_cur[d], 1);
            d_csr[d_off[d] + p] = src[i];
        }
        return;
    }
    constexpr int AROW = 272;
    constexpr int WROW = (COLS == 128) ? 272 : 144;
    constexpr int NT = COLS / 8;

    extern __shared__ char sm[];
    char* smA = sm;
    char* smW = sm + 128 * AROW;
    const unsigned sA = (unsigned)__cvta_generic_to_shared(smA);
    const unsigned sW = (unsigned)__cvta_generic_to_shared(smW);

    const int tid = threadIdx.x;
    const int base = (blockIdx.x - (FILL ? fillBlocks : 0)) * 128;

    for (int i = tid; i < 128 * 32; i += 256) {
        int r = i >> 5, k4 = i & 31;
        int row = base + r;
        uint2 v = make_uint2(0u, 0u);
        if (row < N) v = loadH4(A, (size_t)row, k4);
        *(uint2*)(smA + r * AROW + k4 * 8) = v;
    }
    for (int i = tid; i < 128 * COLS / 4; i += 256) {
        int r = i / (COLS / 4), n4 = i % (COLS / 4);
        float4 v = __ldg((const float4*)W + i);
        __half2 h0 = __floats2half2_rn(v.x, v.y);
        __half2 h1 = __floats2half2_rn(v.z, v.w);
        uint2 u;
        u.x = *(unsigned*)&h0;
        u.y = *(unsigned*)&h1;
        *(uint2*)(smW + r * WROW + n4 * 8) = u;
    }
    __syncthreads();

    const int warp = tid >> 5;
    const int lane = tid & 31;
    const int warprow = warp * 16;
    const int lr = lane & 7;
    const int sel = lane >> 3;
    const int selLo = sel & 1;
    const int selHi = sel >> 1;

    float c[NT][4];
#pragma unroll
    for (int n = 0; n < NT; n++)
#pragma unroll
        for (int q = 0; q < 4; q++) c[n][q] = 0.f;

#pragma unroll
    for (int ks = 0; ks < 8; ks++) {
        unsigned a0, a1, a2, a3;
        unsigned aaddr = sA + (warprow + lr + selLo * 8) * AROW + ks * 32 + selHi * 16;
        asm volatile("ldmatrix.sync.aligned.m8n8.x4.shared.b16 {%0,%1,%2,%3}, [%4];"
                     : "=r"(a0), "=r"(a1), "=r"(a2), "=r"(a3) : "r"(aaddr));
#pragma unroll
        for (int p = 0; p < NT / 2; p++) {
            unsigned b0, b1, b2, b3;
            unsigned baddr = sW + (ks * 16 + lr + selLo * 8) * WROW + p * 32 + selHi * 16;
            asm volatile("ldmatrix.sync.aligned.m8n8.x4.trans.shared.b16 {%0,%1,%2,%3}, [%4];"
                         : "=r"(b0), "=r"(b1), "=r"(b2), "=r"(b3) : "r"(baddr));
            asm volatile("mma.sync.aligned.m16n8k16.row.col.f32.f16.f16.f32 "
                         "{%0,%1,%2,%3}, {%4,%5,%6,%7}, {%8,%9}, {%0,%1,%2,%3};"
                         : "+f"(c[2 * p][0]), "+f"(c[2 * p][1]), "+f"(c[2 * p][2]), "+f"(c[2 * p][3])
                         : "r"(a0), "r"(a1), "r"(a2), "r"(a3), "r"(b0), "r"(b1));
            asm volatile("mma.sync.aligned.m16n8k16.row.col.f32.f16.f16.f32 "
                         "{%0,%1,%2,%3}, {%4,%5,%6,%7}, {%8,%9}, {%0,%1,%2,%3};"
                         : "+f"(c[2 * p + 1][0]), "+f"(c[2 * p + 1][1]), "+f"(c[2 * p + 1][2]), "+f"(c[2 * p + 1][3])
                         : "r"(a0), "r"(a1), "r"(a2), "r"(a3), "r"(b2), "r"(b3));
        }
    }

    const int gq = lane >> 2;
    const int tig = lane & 3;
    int row0 = base + warprow + gq;
    int row1 = row0 + 8;
    float dv0 = (row0 < N) ? d_dinv[row0] : 0.f;
    float dv1 = (row1 < N) ? d_dinv[row1] : 0.f;
#pragma unroll
    for (int n = 0; n < NT; n++) {
        int col = n * 8 + 2 * tig;
        if (row0 < N) {
            __half2 h = __floats2half2_rn(c[n][0] * dv0, c[n][1] * dv0);
            *(__half2*)(g + (size_t)row0 * COLS + col) = h;
        }
        if (row1 < N) {
            __half2 h = __floats2half2_rn(c[n][2] * dv1, c[n][3] * dv1);
            *(__half2*)(g + (size_t)row1 * COLS + col) = h;
        }
    }
}

// ================= CSR aggregate (half msgs, fp32 accum, 1 warp/node) ============
// 8-deep software pipeline: 8 row loads in flight while the NEXT 8 indices load.
__device__ __forceinline__ void acc_u2(float& a0, float& a1, float& a2, float& a3, uint2 v) {
    float2 f0 = __half22float2(*(__half2*)&v.x);
    float2 f1 = __half22float2(*(__half2*)&v.y);
    a0 += f0.x; a1 += f0.y; a2 += f1.x; a3 += f1.y;
}

__global__ void k_agg128(const __half* __restrict__ g, const float* __restrict__ bias,
                         __half* __restrict__ out, int N)
{
    int node = (blockIdx.x * blockDim.x + threadIdx.x) >> 5;
    int lane = threadIdx.x & 31;
    if (node >= N) return;
    const uint2* gp = (const uint2*)g;

    float a0 = 0.f, a1 = 0.f, a2 = 0.f, a3 = 0.f;
    acc_u2(a0, a1, a2, a3, __ldg(&gp[(size_t)node * 32 + lane]));   // self-loop
    int s = d_off[node], e = d_off[node + 1];
    int j = s;
    int c0, c1, c2, c3, c4, c5, c6, c7;
    bool have = (j + 8 <= e);
    if (have) {
        c0 = __ldg(d_csr + j);     c1 = __ldg(d_csr + j + 1);
        c2 = __ldg(d_csr + j + 2); c3 = __ldg(d_csr + j + 3);
        c4 = __ldg(d_csr + j + 4); c5 = __ldg(d_csr + j + 5);
        c6 = __ldg(d_csr + j + 6); c7 = __ldg(d_csr + j + 7);
    }
    while (have) {
        bool nxt = (j + 16 <= e);
        int m0, m1, m2, m3, m4, m5, m6, m7;
        if (nxt) {
            m0 = __ldg(d_csr + j + 8);  m1 = __ldg(d_csr + j + 9);
            m2 = __ldg(d_csr + j + 10); m3 = __ldg(d_csr + j + 11);
            m4 = __ldg(d_csr + j + 12); m5 = __ldg(d_csr + j + 13);
            m6 = __ldg(d_csr + j + 14); m7 = __ldg(d_csr + j + 15);
        }
        uint2 v0 = __ldg(&gp[(size_t)c0 * 32 + lane]);
        uint2 v1 = __ldg(&gp[(size_t)c1 * 32 + lane]);
        uint2 v2 = __ldg(&gp[(size_t)c2 * 32 + lane]);
        uint2 v3 = __ldg(&gp[(size_t)c3 * 32 + lane]);
        uint2 v4 = __ldg(&gp[(size_t)c4 * 32 + lane]);
        uint2 v5 = __ldg(&gp[(size_t)c5 * 32 + lane]);
        uint2 v6 = __ldg(&gp[(size_t)c6 * 32 + lane]);
        uint2 v7 = __ldg(&gp[(size_t)c7 * 32 + lane]);
        acc_u2(a0, a1, a2, a3, v0); acc_u2(a0, a1, a2, a3, v1);
        acc_u2(a0, a1, a2, a3, v2); acc_u2(a0, a1, a2, a3, v3);
        acc_u2(a0, a1, a2, a3, v4); acc_u2(a0, a1, a2, a3, v5);
        acc_u2(a0, a1, a2, a3, v6); acc_u2(a0, a1, a2, a3, v7);
        c0 = m0; c1 = m1; c2 = m2; c3 = m3;
        c4 = m4; c5 = m5; c6 = m6; c7 = m7;
        j += 8;
        have = nxt;
    }
    if (j + 4 <= e) {
        int n0 = __ldg(d_csr + j),     n1 = __ldg(d_csr + j + 1);
        int n2 = __ldg(d_csr + j + 2), n3 = __ldg(d_csr + j + 3);
        uint2 v0 = __ldg(&gp[(size_t)n0 * 32 + lane]);
        uint2 v1 = __ldg(&gp[(size_t)n1 * 32 + lane]);
        uint2 v2 = __ldg(&gp[(size_t)n2 * 32 + lane]);
        uint2 v3 = __ldg(&gp[(size_t)n3 * 32 + lane]);
        acc_u2(a0, a1, a2, a3, v0); acc_u2(a0, a1, a2, a3, v1);
        acc_u2(a0, a1, a2, a3, v2); acc_u2(a0, a1, a2, a3, v3);
        j += 4;
    }
    for (; j < e; j++)
        acc_u2(a0, a1, a2, a3, __ldg(&gp[(size_t)__ldg(d_csr + j) * 32 + lane]));

    float dv = d_dinv[node];
    float4 b = __ldg((const float4*)bias + lane);
    __half2 h0 = __floats2half2_rn(fmaxf(fmaf(a0, dv, b.x), 0.f),
                                   fmaxf(fmaf(a1, dv, b.y), 0.f));
    __half2 h1 = __floats2half2_rn(fmaxf(fmaf(a2, dv, b.z), 0.f),
                                   fmaxf(fmaf(a3, dv, b.w), 0.f));
    uint2 w;
    w.x = *(unsigned*)&h0;
    w.y = *(unsigned*)&h1;
    ((uint2*)out)[(size_t)node * 32 + lane] = w;
}

// layer 3: COLS=64 -> 32 half2/row; fused min-pool + fused final (last block).
__global__ void k_agg64min(const __half* __restrict__ g, const float* __restrict__ b3,
                           float* __restrict__ out, int N)
{
    __shared__ unsigned sMin[64];
    __shared__ bool lastBlk;
    int tid = threadIdx.x;
    if (tid < 64) sMin[tid] = 0xFFFFFFFFu;
    __syncthreads();

    int node = (blockIdx.x * blockDim.x + tid) >> 5;
    int lane = tid & 31;
    if (node < N) {
        const unsigned* gp = (const unsigned*)g;
        float a0 = 0.f, a1 = 0.f;
        {
            unsigned v = __ldg(&gp[(size_t)node * 32 + lane]);
            float2 f = __half22float2(*(__half2*)&v);
            a0 += f.x; a1 += f.y;
        }
        int s = d_off[node], e = d_off[node + 1];
        int j = s;
        int c0, c1, c2, c3, c4, c5, c6, c7;
        bool have = (j + 8 <= e);
        if (have) {
            c0 = __ldg(d_csr + j);     c1 = __ldg(d_csr + j + 1);
            c2 = __ldg(d_csr + j + 2); c3 = __ldg(d_csr + j + 3);
            c4 = __ldg(d_csr + j + 4); c5 = __ldg(d_csr + j + 5);
            c6 = __ldg(d_csr + j + 6); c7 = __ldg(d_csr + j + 7);
        }
        while (have) {
            bool nxt = (j + 16 <= e);
            int m0, m1, m2, m3, m4, m5, m6, m7;
            if (nxt) {
                m0 = __ldg(d_csr + j + 8);  m1 = __ldg(d_csr + j + 9);
                m2 = __ldg(d_csr + j + 10); m3 = __ldg(d_csr + j + 11);
                m4 = __ldg(d_csr + j + 12); m5 = __ldg(d_csr + j + 13);
                m6 = __ldg(d_csr + j + 14); m7 = __ldg(d_csr + j + 15);
            }
            unsigned v0 = __ldg(&gp[(size_t)c0 * 32 + lane]);
            unsigned v1 = __ldg(&gp[(size_t)c1 * 32 + lane]);
            unsigned v2 = __ldg(&gp[(size_t)c2 * 32 + lane]);
            unsigned v3 = __ldg(&gp[(size_t)c3 * 32 + lane]);
            unsigned v4 = __ldg(&gp[(size_t)c4 * 32 + lane]);
            unsigned v5 = __ldg(&gp[(size_t)c5 * 32 + lane]);
            unsigned v6 = __ldg(&gp[(size_t)c6 * 32 + lane]);
            unsigned v7 = __ldg(&gp[(size_t)c7 * 32 + lane]);
            float2 f;
            f = __half22float2(*(__half2*)&v0); a0 += f.x; a1 += f.y;
            f = __half22float2(*(__half2*)&v1); a0 += f.x; a1 += f.y;
            f = __half22float2(*(__half2*)&v2); a0 += f.x; a1 += f.y;
            f = __half22float2(*(__half2*)&v3); a0 += f.x; a1 += f.y;
            f = __half22float2(*(__half2*)&v4); a0 += f.x; a1 += f.y;
            f = __half22float2(*(__half2*)&v5); a0 += f.x; a1 += f.y;
            f = __half22float2(*(__half2*)&v6); a0 += f.x; a1 += f.y;
            f = __half22float2(*(__half2*)&v7); a0 += f.x; a1 += f.y;
            c0 = m0; c1 = m1; c2 = m2; c3 = m3;
            c4 = m4; c5 = m5; c6 = m6; c7 = m7;
            j += 8;
            have = nxt;
        }
        if (j + 4 <= e) {
            int n0 = __ldg(d_csr + j),     n1 = __ldg(d_csr + j + 1);
            int n2 = __ldg(d_csr + j + 2), n3 = __ldg(d_csr + j + 3);
            unsigned v0 = __ldg(&gp[(size_t)n0 * 32 + lane]);
            unsigned v1 = __ldg(&gp[(size_t)n1 * 32 + lane]);
            unsigned v2 = __ldg(&gp[(size_t)n2 * 32 + lane]);
            unsigned v3 = __ldg(&gp[(size_t)n3 * 32 + lane]);
            float2 f;
            f = __half22float2(*(__half2*)&v0); a0 += f.x; a1 += f.y;
            f = __half22float2(*(__half2*)&v1); a0 += f.x; a1 += f.y;
            f = __half22float2(*(__half2*)&v2); a0 += f.x; a1 += f.y;
            f = __half22float2(*(__half2*)&v3); a0 += f.x; a1 += f.y;
            j += 4;
        }
        for (; j < e; j++) {
            unsigned v = __ldg(&gp[(size_t)__ldg(d_csr + j) * 32 + lane]);
            float2 f = __half22float2(*(__half2*)&v);
            a0 += f.x; a1 += f.y;
        }
        float dv = d_dinv[node];
        atomicMin(&sMin[2 * lane + 0], enc_f(a0 * dv));
        atomicMin(&sMin[2 * lane + 1], enc_f(a1 * dv));
    }
    __syncthreads();
    if (tid < 64) atomicMin(&d_gmin[tid], sMin[tid]);
    __threadfence();
    __syncthreads();
    if (tid == 0) {
        int old = atomicAdd(&d_done, 1);
        lastBlk = (old == (int)gridDim.x - 1);
    }
    __syncthreads();
    if (lastBlk) {
        __threadfence();
        if (tid < 64) out[tid] = dec_f(d_gmin[tid]) + __ldg(b3 + tid);
    }
}

extern "C" void kernel_launch(void* const* d_in, const int* in_sizes, int n_in,
                              void* d_out, int out_size)
{
    const float* x  = (const float*)d_in[0];
    const int*   ei = (const int*)d_in[1];
    const float* W1 = (const float*)d_in[2];
    const float* b1 = (const float*)d_in[3];
    const float* W2 = (const float*)d_in[4];
    const float* b2 = (const float*)d_in[5];
    const float* W3 = (const float*)d_in[6];
    const float* b3 = (const float*)d_in[7];
    float* out = (float*)d_out;

    int N = in_sizes[0] / 128;
    int E = in_sizes[1] / 2;
    const int* src = ei;
    const int* dst = ei + E;

    __half *B1, *B2, *G;
    cudaGetSymbolAddress((void**)&B1, d_B1);
    cudaGetSymbolAddress((void**)&B2, d_B2);
    cudaGetSymbolAddress((void**)&G, d_G);

    const int smem128 = 128 * 272 + 128 * 272;
    const int smem64  = 128 * 272 + 128 * 144;
    cudaFuncSetAttribute(k_gemm_mma<128, true,  float>,  cudaFuncAttributeMaxDynamicSharedMemorySize, smem128);
    cudaFuncSetAttribute(k_gemm_mma<128, false, __half>, cudaFuncAttributeMaxDynamicSharedMemorySize, smem128);
    cudaFuncSetAttribute(k_gemm_mma<64,  false, __half>, cudaFuncAttributeMaxDynamicSharedMemorySize, smem64);

    // CSR: hist + scans (dinv ready after scan3; cnt/cur self-cleaned there)
    k_hist<<<(E / 4 + 255) / 256, 256>>>(dst, E);
    int nblk = (N + 1023) / 1024;
    k_scan1<<<nblk, 256>>>(N);
    k_scan2<<<1, 128>>>(nblk);
    k_scan3<<<(N + 255) / 256, 256>>>(N, E);

    int gb = (N + 127) / 128;
    const int fillBlocks = 512;

    // Layer 1: tensor GEMM (x @ W1 -> G) with CSR fill fused at low block ids
    k_gemm_mma<128, true, float><<<gb + fillBlocks, 256, smem128>>>(x, W1, G, N, src, dst, E, fillBlocks);
    k_agg128<<<(N * 32 + 255) / 256, 256>>>(G, b1, B2, N);

    // Layer 2
    k_gemm_mma<128, false, __half><<<gb, 256, smem128>>>(B2, W2, G, N, nullptr, nullptr, 0, 0);
    k_agg128<<<(N * 32 + 255) / 256, 256>>>(G, b2, B1, N);

    // Layer 3 (64 cols) + fused min-pool + fused final
    k_gemm_mma<64, false, __half><<<gb, 256, smem64>>>(B1, W3, G, N, nullptr, nullptr, 0, 0);
    k_agg64min<<<(N * 32 + 255) / 256, 256>>>(G, b3, out, N);
}